// round 1
// baseline (speedup 1.0000x reference)
#include <cuda_runtime.h>
#include <cstdint>

// ---------------- problem constants ----------------
#define BW_   2048          // number of windows (B_ )
#define NTOK  49            // tokens per window
#define DIMC  256
#define C2    128
#define NH    8
#define HD    16
#define HH    56
#define WWID  56
#define BB    32            // batch
#define EPSV  1e-5f

// ---------------- scratch (device globals; no allocations allowed) --------
__device__ float g_xat [ (size_t)BW_*NTOK*C2 ];      // LN(proj_attn(x))
__device__ float g_xcnn[ (size_t)BB*DIMC*HH*WWID ];  // NCHW cnn branch (post LN)
__device__ float g_t   [ (size_t)BB*DIMC*HH*WWID ];  // post dwconv+bn+gelu
__device__ float g_xcw [ (size_t)BW_*NTOK*C2 ];      // 1x1-conv out, window layout
__device__ float g_xat2[ (size_t)BW_*NTOK*C2 ];      // attention out (post LN)

typedef unsigned long long u64;

__device__ __forceinline__ void fma2(u64 &d, u64 a, u64 b) {
    asm("fma.rn.f32x2 %0, %1, %2, %0;" : "+l"(d) : "l"(a), "l"(b));
}
__device__ __forceinline__ float hsum2(u64 a) {
    union { u64 u; float2 f; } cv; cv.u = a;
    return cv.f.x + cv.f.y;
}
__device__ __forceinline__ float wsum(float v) {
    #pragma unroll
    for (int o = 16; o; o >>= 1) v += __shfl_xor_sync(0xffffffffu, v, o);
    return v;
}

// ---------------- shared GEMM helper ----------------
// ys[56][NC] (stride YST) = xs[56][K] (stride XST) @ W^T.
// W rows are [out][K]; cols < n0 come from W0, cols >= n0 from W1.
// 256 threads: cg = tid&31 owns NC/32 consecutive cols (CPT per pass),
// rg = tid>>5 owns rows rg*7 .. rg*7+6. Accumulate in packed f32x2.
template<int K, int NC, int CPT, int XST, int YST>
__device__ __forceinline__ void gemm56(const float* __restrict__ xs,
                                       const float* __restrict__ W0, int n0,
                                       const float* __restrict__ W1,
                                       float* __restrict__ ys)
{
    const int tid  = threadIdx.x;
    const int cg   = tid & 31;
    const int rg   = tid >> 5;
    const int rbase = rg * 7;
    constexpr int NPASS = NC / (32 * CPT);

    #pragma unroll
    for (int pass = 0; pass < NPASS; ++pass) {
        const int c0 = cg * (NC / 32) + pass * CPT;
        const float* wp[CPT];
        #pragma unroll
        for (int j = 0; j < CPT; ++j) {
            int c = c0 + j;
            wp[j] = (c < n0) ? (W0 + (size_t)c * K) : (W1 + (size_t)(c - n0) * K);
        }
        u64 acc[7][CPT];
        #pragma unroll
        for (int r = 0; r < 7; ++r)
            #pragma unroll
            for (int j = 0; j < CPT; ++j) acc[r][j] = 0ull;

        #pragma unroll 2
        for (int k = 0; k < K; k += 4) {
            ulonglong2 xv[7];
            #pragma unroll
            for (int r = 0; r < 7; ++r)
                xv[r] = *(const ulonglong2*)(xs + (rbase + r) * XST + k);
            #pragma unroll
            for (int j = 0; j < CPT; ++j) {
                ulonglong2 wv = *(const ulonglong2*)(wp[j] + k);
                #pragma unroll
                for (int r = 0; r < 7; ++r) {
                    fma2(acc[r][j], xv[r].x, wv.x);
                    fma2(acc[r][j], xv[r].y, wv.y);
                }
            }
        }
        #pragma unroll
        for (int j = 0; j < CPT; ++j)
            #pragma unroll
            for (int r = 0; r < 7; ++r)
                ys[(rbase + r) * YST + c0 + j] = hsum2(acc[r][j]);
    }
}

// ================= K1: dual projection + LN + NCHW scatter =================
// smem: xs 56*256, ys 56*385
__global__ __launch_bounds__(256)
void k1_proj(const float* __restrict__ x,
             const float* __restrict__ pa_w, const float* __restrict__ pa_b,
             const float* __restrict__ pa_g, const float* __restrict__ pa_be,
             const float* __restrict__ pc_w, const float* __restrict__ pc_b,
             const float* __restrict__ pc_g, const float* __restrict__ pc_be)
{
    extern __shared__ float sm[];
    float* xs = sm;               // 56*256
    float* ys = sm + 56 * 256;    // 56*385
    const int bw  = blockIdx.x;
    const int tid = threadIdx.x;

    const float4* gx = (const float4*)(x + (size_t)bw * NTOK * DIMC);
    float4* xs4 = (float4*)xs;
    for (int i = tid; i < 56 * 64; i += 256) {
        int row = i >> 6;
        xs4[i] = (row < NTOK) ? gx[i] : make_float4(0.f, 0.f, 0.f, 0.f);
    }
    __syncthreads();

    gemm56<256, 384, 6, 256, 385>(xs, pa_w, 128, pc_w, ys);
    __syncthreads();

    const int wid = tid >> 5, lane = tid & 31;
    for (int r = wid; r < NTOK; r += 8) {
        float* yr = ys + r * 385;
        // --- attention branch: cols 0..127, +pa_b, LN(pa_g,pa_be) -> g_xat
        float va[4];
        float s = 0.f;
        #pragma unroll
        for (int k = 0; k < 4; ++k) {
            int c = lane + k * 32;
            va[k] = yr[c] + pa_b[c]; s += va[k];
        }
        float m = wsum(s) * (1.f / 128.f);
        float q = 0.f;
        #pragma unroll
        for (int k = 0; k < 4; ++k) { va[k] -= m; q += va[k] * va[k]; }
        float inv = rsqrtf(wsum(q) * (1.f / 128.f) + EPSV);
        float* oa = g_xat + ((size_t)bw * NTOK + r) * C2;
        #pragma unroll
        for (int k = 0; k < 4; ++k) {
            int c = lane + k * 32;
            oa[c] = va[k] * inv * pa_g[c] + pa_be[c];
        }
        // --- cnn branch: cols 128..383, +pc_b, LN(pc_g,pc_be) -> back to ys
        float vc[8];
        s = 0.f;
        #pragma unroll
        for (int k = 0; k < 8; ++k) {
            int c = lane + k * 32;
            vc[k] = yr[128 + c] + pc_b[c]; s += vc[k];
        }
        m = wsum(s) * (1.f / 256.f);
        q = 0.f;
        #pragma unroll
        for (int k = 0; k < 8; ++k) { vc[k] -= m; q += vc[k] * vc[k]; }
        inv = rsqrtf(wsum(q) * (1.f / 256.f) + EPSV);
        #pragma unroll
        for (int k = 0; k < 8; ++k) {
            int c = lane + k * 32;
            yr[128 + c] = vc[k] * inv * pc_g[c] + pc_be[c];
        }
    }
    __syncthreads();

    // scatter cnn branch to NCHW  (7 contiguous floats per (ch,row))
    const int b = bw >> 6, wi = bw & 63, wr = wi >> 3, wc = wi & 7;
    for (int i = tid; i < DIMC * NTOK; i += 256) {
        int ch = i / NTOK, n = i % NTOK;
        int h = wr * 7 + n / 7, w = wc * 7 + n % 7;
        g_xcnn[((size_t)(b * DIMC + ch) * HH + h) * WWID + w] = ys[n * 385 + 128 + ch];
    }
}

// ================= K2: depthwise 3x3 conv + BN + GELU =================
__global__ __launch_bounds__(256)
void k2_dwconv(const float* __restrict__ dw_w, const float* __restrict__ dw_b,
               const float* __restrict__ bn_g, const float* __restrict__ bn_b,
               const float* __restrict__ bn_m, const float* __restrict__ bn_v)
{
    const int bc = blockIdx.x;          // b*256 + c
    const int c  = bc & 255;
    const float* in  = g_xcnn + (size_t)bc * (HH * WWID);
    float*       out = g_t    + (size_t)bc * (HH * WWID);
    float w[9];
    #pragma unroll
    for (int k = 0; k < 9; ++k) w[k] = dw_w[c * 9 + k];
    const float sc = bn_g[c] * rsqrtf(bn_v[c] + EPSV);
    const float sh = bn_b[c] - bn_m[c] * sc;
    const float db = dw_b[c];

    for (int p = threadIdx.x; p < HH * WWID; p += 256) {
        int hh = p / WWID, ww = p % WWID;
        float acc = db;
        #pragma unroll
        for (int i = 0; i < 3; ++i) {
            int y = hh + i - 1;
            if ((unsigned)y >= HH) continue;
            #pragma unroll
            for (int j = 0; j < 3; ++j) {
                int xq = ww + j - 1;
                if ((unsigned)xq >= WWID) continue;
                acc += in[y * WWID + xq] * w[i * 3 + j];
            }
        }
        float v = acc * sc + sh;
        out[p] = 0.5f * v * (1.0f + erff(v * 0.70710678118654752f));
    }
}

// ================= K3: 1x1 conv (gather pixels of window) =================
// smem: xs 56*264 (padded stride), ys 56*129
__global__ __launch_bounds__(256)
void k3_proj2(const float* __restrict__ pr_w, const float* __restrict__ pr_b)
{
    extern __shared__ float sm[];
    float* xs = sm;               // 56*264
    float* ys = sm + 56 * 264;    // 56*129
    const int bw  = blockIdx.x;
    const int tid = threadIdx.x;
    const int b = bw >> 6, wi = bw & 63, wr = wi >> 3, wc = wi & 7;

    // zero pad rows 49..55
    for (int i = tid; i < 7 * 264; i += 256) xs[49 * 264 + i] = 0.f;
    // gather: xs[n][c] = t[b][c][h][w]
    for (int i = tid; i < DIMC * NTOK; i += 256) {
        int c = i / NTOK, n = i % NTOK;
        int h = wr * 7 + n / 7, w = wc * 7 + n % 7;
        xs[n * 264 + c] = g_t[((size_t)(b * DIMC + c) * HH + h) * WWID + w];
    }
    __syncthreads();

    gemm56<256, 128, 4, 264, 129>(xs, pr_w, 128, pr_w, ys);
    __syncthreads();

    float* o = g_xcw + (size_t)bw * NTOK * C2;
    for (int i = tid; i < NTOK * C2; i += 256) {
        int r = i / C2, c = i % C2;
        o[i] = ys[r * 129 + c] + pr_b[c];
    }
}

// ================= K4: qkv + MHSA + LN =================
// smem: xs 56*128, ys 56*385, sc 8*2401, rpb 1352, rpi 2401(int)
__global__ __launch_bounds__(256)
void k4_attn(const float* __restrict__ qkv_w, const float* __restrict__ qkv_b,
             const float* __restrict__ rpb,   const int* __restrict__ rpi,
             const float* __restrict__ an_g,  const float* __restrict__ an_be)
{
    extern __shared__ float sm[];
    float* xs   = sm;                       // 56*128  = 7168
    float* ys   = xs + 56 * 128;            // 56*385  = 21560
    float* sc   = ys + 56 * 385;            // 8*2401  = 19208
    float* rpbs = sc + 8 * 2401;            // 1352
    int*   rpis = (int*)(rpbs + 1352);      // 2401
    const int bw  = blockIdx.x;
    const int tid = threadIdx.x;

    const float4* gx = (const float4*)(g_xat + (size_t)bw * NTOK * C2);
    float4* xs4 = (float4*)xs;
    for (int i = tid; i < 56 * 32; i += 256) {
        int row = i >> 5;
        xs4[i] = (row < NTOK) ? gx[i] : make_float4(0.f, 0.f, 0.f, 0.f);
    }
    for (int i = tid; i < 1352; i += 256) rpbs[i] = rpb[i];
    for (int i = tid; i < 2401; i += 256) rpis[i] = rpi[i];
    __syncthreads();

    gemm56<128, 384, 6, 128, 385>(xs, qkv_w, 384, qkv_w, ys);
    __syncthreads();

    // add qkv bias
    for (int i = tid; i < NTOK * 384; i += 256)
        ys[(i / 384) * 385 + (i % 384)] += qkv_b[i % 384];
    __syncthreads();

    // per-head attention: warp h handles head h
    const int h = tid >> 5, lane = tid & 31;
    float* sh_ = sc + h * 2401;
    for (int pass = 0; pass < 2; ++pass) {
        int n = pass * 32 + lane;
        if (n < NTOK) {
            float q[16];
            #pragma unroll
            for (int d = 0; d < 16; ++d) q[d] = ys[n * 385 + h * 16 + d];
            float mx = -1e30f;
            for (int m = 0; m < NTOK; ++m) {
                float s = 0.f;
                #pragma unroll
                for (int d = 0; d < 16; ++d)
                    s += q[d] * ys[m * 385 + 128 + h * 16 + d];
                s = s * 0.25f + rpbs[rpis[n * NTOK + m] * NH + h];
                sh_[n * NTOK + m] = s;
                mx = fmaxf(mx, s);
            }
            float sum = 0.f;
            for (int m = 0; m < NTOK; ++m) {
                float e = __expf(sh_[n * NTOK + m] - mx);
                sh_[n * NTOK + m] = e; sum += e;
            }
            float inv = 1.f / sum;
            float o[16];
            #pragma unroll
            for (int d = 0; d < 16; ++d) o[d] = 0.f;
            for (int m = 0; m < NTOK; ++m) {
                float p = sh_[n * NTOK + m];
                #pragma unroll
                for (int d = 0; d < 16; ++d)
                    o[d] += p * ys[m * 385 + 256 + h * 16 + d];
            }
            #pragma unroll
            for (int d = 0; d < 16; ++d)
                xs[n * 128 + h * 16 + d] = o[d] * inv;
        }
    }
    __syncthreads();

    // LN over 128 dims -> g_xat2
    const int wid = h;
    for (int r = wid; r < NTOK; r += 8) {
        float va[4];
        float s = 0.f;
        #pragma unroll
        for (int k = 0; k < 4; ++k) { va[k] = xs[r * 128 + lane + k * 32]; s += va[k]; }
        float m = wsum(s) * (1.f / 128.f);
        float qq = 0.f;
        #pragma unroll
        for (int k = 0; k < 4; ++k) { va[k] -= m; qq += va[k] * va[k]; }
        float inv = rsqrtf(wsum(qq) * (1.f / 128.f) + EPSV);
        float* oa = g_xat2 + ((size_t)bw * NTOK + r) * C2;
        #pragma unroll
        for (int k = 0; k < 4; ++k) {
            int c = lane + k * 32;
            oa[c] = va[k] * inv * an_g[c] + an_be[c];
        }
    }
}

// ================= K5: concat + final projection =================
// smem: xs 56*256, ys 56*257
__global__ __launch_bounds__(256)
void k5_out(const float* __restrict__ po_w, const float* __restrict__ po_b,
            float* __restrict__ out)
{
    extern __shared__ float sm[];
    float* xs = sm;               // 56*256
    float* ys = sm + 56 * 256;    // 56*257
    const int bw  = blockIdx.x;
    const int tid = threadIdx.x;

    const float4* ga = (const float4*)(g_xat2 + (size_t)bw * NTOK * C2);
    const float4* gc = (const float4*)(g_xcw  + (size_t)bw * NTOK * C2);
    float4* xs4 = (float4*)xs;
    for (int i = tid; i < 56 * 64; i += 256) {
        int row = i >> 6, c4 = i & 63;
        float4 v = make_float4(0.f, 0.f, 0.f, 0.f);
        if (row < NTOK)
            v = (c4 < 32) ? ga[row * 32 + c4] : gc[row * 32 + (c4 - 32)];
        xs4[i] = v;
    }
    __syncthreads();

    gemm56<256, 256, 4, 256, 257>(xs, po_w, 256, po_w, ys);
    __syncthreads();

    float* o = out + (size_t)bw * NTOK * DIMC;
    for (int i = tid; i < NTOK * DIMC; i += 256) {
        int r = i / DIMC, c = i % DIMC;
        o[i] = ys[r * 257 + c] + po_b[c];
    }
}

// ================= host launch =================
extern "C" void kernel_launch(void* const* d_in, const int* in_sizes, int n_in,
                              void* d_out, int out_size)
{
    const float* x     = (const float*)d_in[0];
    const float* rpb   = (const float*)d_in[1];
    const float* pa_w  = (const float*)d_in[2];
    const float* pa_b  = (const float*)d_in[3];
    const float* pa_g  = (const float*)d_in[4];
    const float* pa_be = (const float*)d_in[5];
    const float* pc_w  = (const float*)d_in[6];
    const float* pc_b  = (const float*)d_in[7];
    const float* pc_g  = (const float*)d_in[8];
    const float* pc_be = (const float*)d_in[9];
    const float* dw_w  = (const float*)d_in[10];
    const float* dw_b  = (const float*)d_in[11];
    const float* bn_g  = (const float*)d_in[12];
    const float* bn_b  = (const float*)d_in[13];
    const float* bn_m  = (const float*)d_in[14];
    const float* bn_v  = (const float*)d_in[15];
    const float* pr_w  = (const float*)d_in[16];
    const float* pr_b  = (const float*)d_in[17];
    const float* qkv_w = (const float*)d_in[18];
    const float* qkv_b = (const float*)d_in[19];
    const float* an_g  = (const float*)d_in[20];
    const float* an_be = (const float*)d_in[21];
    const float* po_w  = (const float*)d_in[22];
    const float* po_b  = (const float*)d_in[23];
    const int*   rpi   = (const int*)  d_in[24];

    const int smem1 = (56 * 256 + 56 * 385) * 4;                    // 143,584
    const int smem3 = (56 * 264 + 56 * 129) * 4;                    //  88,032
    const int smem4 = (56 * 128 + 56 * 385 + 8 * 2401 + 1352 + 2401) * 4; // 206,756
    const int smem5 = (56 * 256 + 56 * 257) * 4;                    // 114,912

    cudaFuncSetAttribute(k1_proj,  cudaFuncAttributeMaxDynamicSharedMemorySize, smem1);
    cudaFuncSetAttribute(k3_proj2, cudaFuncAttributeMaxDynamicSharedMemorySize, smem3);
    cudaFuncSetAttribute(k4_attn,  cudaFuncAttributeMaxDynamicSharedMemorySize, smem4);
    cudaFuncSetAttribute(k5_out,   cudaFuncAttributeMaxDynamicSharedMemorySize, smem5);

    k1_proj <<<BW_, 256, smem1>>>(x, pa_w, pa_b, pa_g, pa_be, pc_w, pc_b, pc_g, pc_be);
    k2_dwconv<<<BB * DIMC, 256>>>(dw_w, dw_b, bn_g, bn_b, bn_m, bn_v);
    k3_proj2<<<BW_, 256, smem3>>>(pr_w, pr_b);
    k4_attn <<<BW_, 256, smem4>>>(qkv_w, qkv_b, rpb, rpi, an_g, an_be);
    k5_out  <<<BW_, 256, smem5>>>(po_w, po_b, (float*)d_out);
}

// round 2
// speedup vs baseline: 5.0532x; 5.0532x over previous
#include <cuda_runtime.h>
#include <cstdint>

#define BW_   2048
#define NTOK  49
#define DIMC  256
#define C2    128
#define NH    8
#define M_TOT (BW_*NTOK)     // 100352
#define EPSV  1e-5f
#define SA    132            // smem tile stride (floats)

// ---------------- scratch ----------------
__device__ float g_y1  [(size_t)M_TOT*384];
__device__ float g_xat [(size_t)M_TOT*C2];
__device__ float g_xc  [(size_t)M_TOT*DIMC];
__device__ float g_d   [(size_t)M_TOT*DIMC];
__device__ float g_qkv [(size_t)M_TOT*384];
__device__ float g_xcw [(size_t)M_TOT*C2];
__device__ float g_xat2[(size_t)M_TOT*C2];

typedef unsigned long long u64;
union F4U2 { float4 f; ulonglong2 u; };
union U2F  { u64 u; float2 f; };

__device__ __forceinline__ void fma2(u64 &d, u64 a, u64 b) {
    asm("fma.rn.f32x2 %0, %1, %2, %0;" : "+l"(d) : "l"(a), "l"(b));
}
__device__ __forceinline__ u64 dup(float w) {
    U2F t; t.f.x = w; t.f.y = w; return t.u;
}
__device__ __forceinline__ float wsum(float v) {
    #pragma unroll
    for (int o = 16; o; o >>= 1) v += __shfl_xor_sync(0xffffffffu, v, o);
    return v;
}

// ================= tiled GEMM: C[M,N] = A[M,K] @ W[N,K]^T (+bias) =========
// 128x128 tile, Ktile 16, 256 threads, 8x8 per thread, f32x2 accumulators.
// W rows < nsplit come from W0, >= nsplit from W1 (for concatenated weights).
// SPLITA: A columns k<128 from A0, k>=128 from A1 (each row-stride 128).
template<int K, bool SPLITA>
__global__ __launch_bounds__(256)
void k_gemm(const float* __restrict__ A0, const float* __restrict__ A1,
            const float* __restrict__ W0, const float* __restrict__ W1, int nsplit,
            const float* __restrict__ bias, float* __restrict__ C, int N)
{
    extern __shared__ float sm[];
    float* As = sm;                 // [2][16][SA]
    float* Ws = sm + 2 * 16 * SA;   // [2][16][SA]
    const int tid = threadIdx.x;
    const int m0 = blockIdx.x * 128;
    const int n0 = blockIdx.y * 128;
    constexpr int NCH = K / 16;

    const int lr = tid >> 2;        // 0..63 (row within tile; +64 for 2nd)
    const int lq = tid & 3;         // which float4 of the 16-k chunk

    // W row pointers
    int nA = n0 + lr, nB = n0 + lr + 64;
    const float* wpA = (nA < nsplit) ? (W0 + (size_t)nA * K) : (W1 + (size_t)(nA - nsplit) * K);
    const float* wpB = (nB < nsplit) ? (W0 + (size_t)nB * K) : (W1 + (size_t)(nB - nsplit) * K);

    const int mr = (tid >> 4) * 8;
    const int nc = (tid & 15) * 8;
    u64 acc[32];
    #pragma unroll
    for (int i = 0; i < 32; ++i) acc[i] = 0ull;

    float4 a0v, a1v, w0v, w1v;

    // --- chunk loader (global -> regs) ---
    auto loadAB = [&](int ch, float4& ra0, float4& ra1, float4& rw0, float4& rw1) {
        int kk = ch * 16 + lq * 4;
        if (SPLITA) {
            const float* b0 = (kk < 128) ? (A0 + (size_t)(m0 + lr) * 128 + kk)
                                         : (A1 + (size_t)(m0 + lr) * 128 + kk - 128);
            const float* b1 = (kk < 128) ? (A0 + (size_t)(m0 + lr + 64) * 128 + kk)
                                         : (A1 + (size_t)(m0 + lr + 64) * 128 + kk - 128);
            ra0 = *(const float4*)b0;
            ra1 = *(const float4*)b1;
        } else {
            ra0 = *(const float4*)(A0 + (size_t)(m0 + lr) * K + kk);
            ra1 = *(const float4*)(A0 + (size_t)(m0 + lr + 64) * K + kk);
        }
        rw0 = *(const float4*)(wpA + kk);
        rw1 = *(const float4*)(wpB + kk);
    };
    auto stage = [&](int buf, float4 ra0, float4 ra1, float4 rw0, float4 rw1) {
        float* Ab = As + buf * 16 * SA;
        float* Wb = Ws + buf * 16 * SA;
        int kb = lq * 4;
        Ab[(kb+0)*SA + lr]      = ra0.x; Ab[(kb+1)*SA + lr]      = ra0.y;
        Ab[(kb+2)*SA + lr]      = ra0.z; Ab[(kb+3)*SA + lr]      = ra0.w;
        Ab[(kb+0)*SA + lr + 64] = ra1.x; Ab[(kb+1)*SA + lr + 64] = ra1.y;
        Ab[(kb+2)*SA + lr + 64] = ra1.z; Ab[(kb+3)*SA + lr + 64] = ra1.w;
        Wb[(kb+0)*SA + lr]      = rw0.x; Wb[(kb+1)*SA + lr]      = rw0.y;
        Wb[(kb+2)*SA + lr]      = rw0.z; Wb[(kb+3)*SA + lr]      = rw0.w;
        Wb[(kb+0)*SA + lr + 64] = rw1.x; Wb[(kb+1)*SA + lr + 64] = rw1.y;
        Wb[(kb+2)*SA + lr + 64] = rw1.z; Wb[(kb+3)*SA + lr + 64] = rw1.w;
    };

    loadAB(0, a0v, a1v, w0v, w1v);
    stage(0, a0v, a1v, w0v, w1v);
    __syncthreads();

    for (int ch = 0; ch < NCH; ++ch) {
        const int buf = ch & 1;
        if (ch + 1 < NCH) loadAB(ch + 1, a0v, a1v, w0v, w1v);
        const float* Ab = As + buf * 16 * SA;
        const float* Wb = Ws + buf * 16 * SA;
        #pragma unroll
        for (int k = 0; k < 16; ++k) {
            F4U2 au0, au1;
            au0.f = *(const float4*)(Ab + k * SA + mr);
            au1.f = *(const float4*)(Ab + k * SA + mr + 4);
            float4 w0 = *(const float4*)(Wb + k * SA + nc);
            float4 w1 = *(const float4*)(Wb + k * SA + nc + 4);
            u64 ap[4] = { au0.u.x, au0.u.y, au1.u.x, au1.u.y };
            u64 wd[8] = { dup(w0.x), dup(w0.y), dup(w0.z), dup(w0.w),
                          dup(w1.x), dup(w1.y), dup(w1.z), dup(w1.w) };
            #pragma unroll
            for (int p = 0; p < 4; ++p)
                #pragma unroll
                for (int c = 0; c < 8; ++c)
                    fma2(acc[p * 8 + c], ap[p], wd[c]);
        }
        if (ch + 1 < NCH) {
            __syncthreads();
            stage((ch + 1) & 1, a0v, a1v, w0v, w1v);
            __syncthreads();
        }
    }

    float bv[8];
    #pragma unroll
    for (int j = 0; j < 8; ++j) bv[j] = bias ? bias[n0 + nc + j] : 0.f;
    #pragma unroll
    for (int p = 0; p < 4; ++p) {
        const int r0 = m0 + mr + 2 * p;
        U2F t[8];
        #pragma unroll
        for (int c = 0; c < 8; ++c) t[c].u = acc[p * 8 + c];
        float4 lo0 = make_float4(t[0].f.x + bv[0], t[1].f.x + bv[1], t[2].f.x + bv[2], t[3].f.x + bv[3]);
        float4 lo1 = make_float4(t[4].f.x + bv[4], t[5].f.x + bv[5], t[6].f.x + bv[6], t[7].f.x + bv[7]);
        float4 hi0 = make_float4(t[0].f.y + bv[0], t[1].f.y + bv[1], t[2].f.y + bv[2], t[3].f.y + bv[3]);
        float4 hi1 = make_float4(t[4].f.y + bv[4], t[5].f.y + bv[5], t[6].f.y + bv[6], t[7].f.y + bv[7]);
        *(float4*)(C + (size_t)r0 * N + n0 + nc)           = lo0;
        *(float4*)(C + (size_t)r0 * N + n0 + nc + 4)       = lo1;
        *(float4*)(C + (size_t)(r0 + 1) * N + n0 + nc)     = hi0;
        *(float4*)(C + (size_t)(r0 + 1) * N + n0 + nc + 4) = hi1;
    }
}

// ================= E1: dual LayerNorm epilogue of G1 =================
__global__ __launch_bounds__(256)
void k_ln1(const float* __restrict__ pa_b, const float* __restrict__ pa_g,
           const float* __restrict__ pa_be,
           const float* __restrict__ pc_b, const float* __restrict__ pc_g,
           const float* __restrict__ pc_be)
{
    const int row  = blockIdx.x * 8 + (threadIdx.x >> 5);
    const int lane = threadIdx.x & 31;
    const float4* y4 = (const float4*)(g_y1 + (size_t)row * 384);

    // attention branch: cols 0..127
    float4 va = y4[lane];
    float4 b  = ((const float4*)pa_b)[lane];
    va.x += b.x; va.y += b.y; va.z += b.z; va.w += b.w;
    float m = wsum(va.x + va.y + va.z + va.w) * (1.f / 128.f);
    va.x -= m; va.y -= m; va.z -= m; va.w -= m;
    float inv = rsqrtf(wsum(va.x*va.x + va.y*va.y + va.z*va.z + va.w*va.w) * (1.f / 128.f) + EPSV);
    float4 g  = ((const float4*)pa_g)[lane];
    float4 be = ((const float4*)pa_be)[lane];
    float4 o;
    o.x = va.x * inv * g.x + be.x; o.y = va.y * inv * g.y + be.y;
    o.z = va.z * inv * g.z + be.z; o.w = va.w * inv * g.w + be.w;
    *(float4*)(g_xat + (size_t)row * 128 + lane * 4) = o;

    // cnn branch: cols 128..383
    float4 c0 = y4[32 + lane], c1 = y4[64 + lane];
    float4 b0 = ((const float4*)pc_b)[lane], b1 = ((const float4*)pc_b)[32 + lane];
    c0.x += b0.x; c0.y += b0.y; c0.z += b0.z; c0.w += b0.w;
    c1.x += b1.x; c1.y += b1.y; c1.z += b1.z; c1.w += b1.w;
    m = wsum(c0.x + c0.y + c0.z + c0.w + c1.x + c1.y + c1.z + c1.w) * (1.f / 256.f);
    c0.x -= m; c0.y -= m; c0.z -= m; c0.w -= m;
    c1.x -= m; c1.y -= m; c1.z -= m; c1.w -= m;
    inv = rsqrtf(wsum(c0.x*c0.x + c0.y*c0.y + c0.z*c0.z + c0.w*c0.w +
                      c1.x*c1.x + c1.y*c1.y + c1.z*c1.z + c1.w*c1.w) * (1.f / 256.f) + EPSV);
    float4 g0 = ((const float4*)pc_g)[lane],  g1 = ((const float4*)pc_g)[32 + lane];
    float4 e0 = ((const float4*)pc_be)[lane], e1 = ((const float4*)pc_be)[32 + lane];
    float4 o0, o1;
    o0.x = c0.x * inv * g0.x + e0.x; o0.y = c0.y * inv * g0.y + e0.y;
    o0.z = c0.z * inv * g0.z + e0.z; o0.w = c0.w * inv * g0.w + e0.w;
    o1.x = c1.x * inv * g1.x + e1.x; o1.y = c1.y * inv * g1.y + e1.y;
    o1.z = c1.z * inv * g1.z + e1.z; o1.w = c1.w * inv * g1.w + e1.w;
    *(float4*)(g_xc + (size_t)row * 256 + lane * 4)       = o0;
    *(float4*)(g_xc + (size_t)row * 256 + 128 + lane * 4) = o1;
}

// ================= D: depthwise 3x3 + BN + GELU (window-major) ===========
__global__ __launch_bounds__(256)
void k_dw(const float* __restrict__ dw_w, const float* __restrict__ dw_b,
          const float* __restrict__ bn_g, const float* __restrict__ bn_b,
          const float* __restrict__ bn_m, const float* __restrict__ bn_v)
{
    extern __shared__ float sm[];   // 81 pixels x 256 ch
    const int bw = blockIdx.x, tid = threadIdx.x;
    const int b = bw >> 6, wi = bw & 63, wr = wi >> 3, wc = wi & 7;

    for (int i = tid; i < 81 * 64; i += 256) {
        int pix = i >> 6, c4 = i & 63;
        int gy = wr * 7 + pix / 9 - 1, gx = wc * 7 + pix % 9 - 1;
        float4 v = make_float4(0.f, 0.f, 0.f, 0.f);
        if ((unsigned)gy < 56u && (unsigned)gx < 56u) {
            int wn = b * 64 + (gy / 7) * 8 + gx / 7;
            int tk = (gy % 7) * 7 + gx % 7;
            v = *(const float4*)(g_xc + ((size_t)wn * 49 + tk) * 256 + c4 * 4);
        }
        *(float4*)(sm + pix * 256 + c4 * 4) = v;
    }
    __syncthreads();

    const int c = tid;
    float w[9];
    #pragma unroll
    for (int j = 0; j < 9; ++j) w[j] = dw_w[c * 9 + j];
    const float sc = bn_g[c] * rsqrtf(bn_v[c] + EPSV);
    const float sh = bn_b[c] - bn_m[c] * sc;
    const float db = dw_b[c];
    float* outp = g_d + (size_t)bw * 49 * 256;

    #pragma unroll 7
    for (int p = 0; p < 49; ++p) {
        int oy = p / 7, ox = p % 7;
        float acc = db;
        #pragma unroll
        for (int dy = 0; dy < 3; ++dy)
            #pragma unroll
            for (int dx = 0; dx < 3; ++dx)
                acc += w[dy * 3 + dx] * sm[((oy + dy) * 9 + ox + dx) * 256 + c];
        float v = acc * sc + sh;
        outp[p * 256 + c] = 0.5f * v * (1.0f + erff(v * 0.70710678118654752f));
    }
}

// ================= A: windowed MHSA + LN =================
__global__ __launch_bounds__(256)
void k_attn(const float* __restrict__ rpb,
            const float* __restrict__ an_g, const float* __restrict__ an_be)
{
    extern __shared__ float sm[];
    float* kvs  = sm;                 // 49*256 (k | v)
    float* ss   = sm + 49 * 256;      // 8*32*53 scores
    float* rpbs = ss + 8 * 32 * 53;   // 1352
    const int bw = blockIdx.x, tid = threadIdx.x;
    const int h = tid >> 5, lane = tid & 31;
    const float* qkvw = g_qkv + (size_t)bw * 49 * 384;

    for (int i = tid; i < 49 * 64; i += 256) {
        int r = i >> 6, cc = i & 63;
        *(float4*)(kvs + r * 256 + cc * 4) = *(const float4*)(qkvw + r * 384 + 128 + cc * 4);
    }
    for (int i = tid; i < 1352; i += 256) rpbs[i] = rpb[i];
    __syncthreads();

    float o[2][16];
    #pragma unroll
    for (int pass = 0; pass < 2; ++pass) {
        const int n = pass * 32 + lane;
        if (n < 49) {
            float q[16];
            const float4* qp = (const float4*)(qkvw + n * 384 + h * 16);
            *(float4*)&q[0]  = qp[0]; *(float4*)&q[4]  = qp[1];
            *(float4*)&q[8]  = qp[2]; *(float4*)&q[12] = qp[3];
            const int yn = n / 7, xn = n % 7;
            float* sr = ss + (h * 32 + lane) * 53;
            float mx = -1e30f;
            #pragma unroll 7
            for (int m2 = 0; m2 < 49; ++m2) {
                const float* kr = kvs + m2 * 256 + h * 16;
                float s = 0.f;
                #pragma unroll
                for (int d = 0; d < 16; ++d) s += q[d] * kr[d];
                int dy = yn - m2 / 7 + 6, dx = xn - m2 % 7 + 6;
                s = s * 0.25f + rpbs[(dy * 13 + dx) * NH + h];
                sr[m2] = s; mx = fmaxf(mx, s);
            }
            float sum = 0.f;
            #pragma unroll 7
            for (int m2 = 0; m2 < 49; ++m2) {
                float e = __expf(sr[m2] - mx);
                sr[m2] = e; sum += e;
            }
            const float inv = 1.f / sum;
            float* op = o[pass];
            #pragma unroll
            for (int d = 0; d < 16; ++d) op[d] = 0.f;
            #pragma unroll 7
            for (int m2 = 0; m2 < 49; ++m2) {
                float p = sr[m2];
                const float* vr = kvs + m2 * 256 + 128 + h * 16;
                #pragma unroll
                for (int d = 0; d < 16; ++d) op[d] += p * vr[d];
            }
            #pragma unroll
            for (int d = 0; d < 16; ++d) op[d] *= inv;
        }
    }
    __syncthreads();
    float* xo = kvs;   // reuse as attn output [49][128]
    #pragma unroll
    for (int pass = 0; pass < 2; ++pass) {
        const int n = pass * 32 + lane;
        if (n < 49) {
            #pragma unroll
            for (int d = 0; d < 16; ++d) xo[n * 128 + h * 16 + d] = o[pass][d];
        }
    }
    __syncthreads();

    for (int r = h; r < 49; r += 8) {
        float4 v = *(float4*)(xo + r * 128 + lane * 4);
        float m = wsum(v.x + v.y + v.z + v.w) * (1.f / 128.f);
        v.x -= m; v.y -= m; v.z -= m; v.w -= m;
        float inv = rsqrtf(wsum(v.x*v.x + v.y*v.y + v.z*v.z + v.w*v.w) * (1.f / 128.f) + EPSV);
        float4 g  = ((const float4*)an_g)[lane];
        float4 be = ((const float4*)an_be)[lane];
        float4 out;
        out.x = v.x * inv * g.x + be.x; out.y = v.y * inv * g.y + be.y;
        out.z = v.z * inv * g.z + be.z; out.w = v.w * inv * g.w + be.w;
        *(float4*)(g_xat2 + ((size_t)bw * 49 + r) * 128 + lane * 4) = out;
    }
}

// ================= host launch =================
extern "C" void kernel_launch(void* const* d_in, const int* in_sizes, int n_in,
                              void* d_out, int out_size)
{
    const float* x     = (const float*)d_in[0];
    const float* rpb   = (const float*)d_in[1];
    const float* pa_w  = (const float*)d_in[2];
    const float* pa_b  = (const float*)d_in[3];
    const float* pa_g  = (const float*)d_in[4];
    const float* pa_be = (const float*)d_in[5];
    const float* pc_w  = (const float*)d_in[6];
    const float* pc_b  = (const float*)d_in[7];
    const float* pc_g  = (const float*)d_in[8];
    const float* pc_be = (const float*)d_in[9];
    const float* dw_w  = (const float*)d_in[10];
    const float* dw_b  = (const float*)d_in[11];
    const float* bn_g  = (const float*)d_in[12];
    const float* bn_b  = (const float*)d_in[13];
    const float* bn_m  = (const float*)d_in[14];
    const float* bn_v  = (const float*)d_in[15];
    const float* pr_w  = (const float*)d_in[16];
    const float* pr_b  = (const float*)d_in[17];
    const float* qkv_w = (const float*)d_in[18];
    const float* qkv_b = (const float*)d_in[19];
    const float* an_g  = (const float*)d_in[20];
    const float* an_be = (const float*)d_in[21];
    const float* po_w  = (const float*)d_in[22];
    const float* po_b  = (const float*)d_in[23];

    float *py1, *pxat, *pxc, *pd, *pqkv, *pxcw, *pxat2;
    cudaGetSymbolAddress((void**)&py1,   g_y1);
    cudaGetSymbolAddress((void**)&pxat,  g_xat);
    cudaGetSymbolAddress((void**)&pxc,   g_xc);
    cudaGetSymbolAddress((void**)&pd,    g_d);
    cudaGetSymbolAddress((void**)&pqkv,  g_qkv);
    cudaGetSymbolAddress((void**)&pxcw,  g_xcw);
    cudaGetSymbolAddress((void**)&pxat2, g_xat2);

    const int smG = 2 * 16 * SA * 4 * 2;          // 67,584
    const int smD = 81 * 256 * 4;                 // 82,944
    const int smA = (49*256 + 8*32*53 + 1352) * 4;// 109,856

    cudaFuncSetAttribute(k_gemm<256,false>, cudaFuncAttributeMaxDynamicSharedMemorySize, smG);
    cudaFuncSetAttribute(k_gemm<128,false>, cudaFuncAttributeMaxDynamicSharedMemorySize, smG);
    cudaFuncSetAttribute(k_gemm<256,true>,  cudaFuncAttributeMaxDynamicSharedMemorySize, smG);
    cudaFuncSetAttribute(k_dw,   cudaFuncAttributeMaxDynamicSharedMemorySize, smD);
    cudaFuncSetAttribute(k_attn, cudaFuncAttributeMaxDynamicSharedMemorySize, smA);

    const int MT = M_TOT / 128;   // 784

    // G1: [x] @ [pa_w; pc_w]^T -> g_y1 (bias deferred to LN)
    k_gemm<256,false><<<dim3(MT,3), 256, smG>>>(x, nullptr, pa_w, pc_w, 128,
                                                nullptr, py1, 384);
    // E1: dual LN -> g_xat, g_xc
    k_ln1<<<M_TOT/8, 256>>>(pa_b, pa_g, pa_be, pc_b, pc_g, pc_be);
    // G3: qkv = g_xat @ qkv_w^T + qkv_b
    k_gemm<128,false><<<dim3(MT,3), 256, smG>>>(pxat, nullptr, qkv_w, qkv_w, 1<<30,
                                                qkv_b, pqkv, 384);
    // D: dwconv + BN + GELU -> g_d
    k_dw<<<BW_, 256, smD>>>(dw_w, dw_b, bn_g, bn_b, bn_m, bn_v);
    // G2: 1x1 conv: g_d @ pr_w^T + pr_b -> g_xcw
    k_gemm<256,false><<<dim3(MT,1), 256, smG>>>(pd, nullptr, pr_w, pr_w, 1<<30,
                                                pr_b, pxcw, 128);
    // A: attention + LN -> g_xat2
    k_attn<<<BW_, 256, smA>>>(rpb, an_g, an_be);
    // G4: concat(g_xat2, g_xcw) @ po_w^T + po_b -> out
    k_gemm<256,true><<<dim3(MT,2), 256, smG>>>(pxat2, pxcw, po_w, po_w, 1<<30,
                                               po_b, (float*)d_out, 256);
}

// round 4
// speedup vs baseline: 7.9304x; 1.5694x over previous
#include <cuda_runtime.h>
#include <cstdint>

#define BW_   2048
#define NTOK  49
#define DIMC  256
#define C2    128
#define NH    8
#define M_TOT (BW_*NTOK)     // 100352
#define EPSV  1e-5f

// A smem: 128 rows x 32 k, stride 36  -> 4608 u32 per buffer
// W smem: 32 k rows x 128 n, stride 136 -> 4352 u32 per buffer
#define ASTR 36
#define WSTR 136
#define ASZ  (128*ASTR)
#define WSZ  (32*WSTR)

// ---------------- scratch ----------------
__device__ float g_y1  [(size_t)M_TOT*384];
__device__ float g_xat [(size_t)M_TOT*C2];
__device__ float g_xc  [(size_t)M_TOT*DIMC];
__device__ float g_d   [(size_t)M_TOT*DIMC];
__device__ float g_qkv [(size_t)M_TOT*384];
__device__ float g_xcw [(size_t)M_TOT*C2];
__device__ float g_xat2[(size_t)M_TOT*C2];

__device__ __forceinline__ float wsum(float v) {
    #pragma unroll
    for (int o = 16; o; o >>= 1) v += __shfl_xor_sync(0xffffffffu, v, o);
    return v;
}
__device__ __forceinline__ uint32_t tf32r(float f) {
    uint32_t r; asm("cvt.rna.tf32.f32 %0, %1;" : "=r"(r) : "f"(f)); return r;
}
__device__ __forceinline__ void mma8(float* c, const uint32_t* a, const uint32_t* b) {
    asm volatile(
        "mma.sync.aligned.m16n8k8.row.col.f32.tf32.tf32.f32 "
        "{%0,%1,%2,%3},{%4,%5,%6,%7},{%8,%9},{%0,%1,%2,%3};"
        : "+f"(c[0]), "+f"(c[1]), "+f"(c[2]), "+f"(c[3])
        : "r"(a[0]), "r"(a[1]), "r"(a[2]), "r"(a[3]), "r"(b[0]), "r"(b[1]));
}

// ============== tf32 tensor GEMM: C[M,N] = A[M,K] @ W^T (+bias) ==========
// 128x128 CTA tile; 8 warps, each m32 x n64; k-chunks of 32.
// W rows < nsplit from W0 else W1. SPLITA: A cols k<128 from A0 else A1.
template<int K, bool SPLITA>
__global__ __launch_bounds__(256)
void k_gemm(const float* __restrict__ A0, const float* __restrict__ A1,
            const float* __restrict__ W0, const float* __restrict__ W1, int nsplit,
            const float* __restrict__ bias, float* __restrict__ C, int N)
{
    extern __shared__ uint32_t smu[];
    uint32_t* Asm = smu;              // [2][ASZ]
    uint32_t* Wsm = smu + 2 * ASZ;    // [2][WSZ]
    const int tid  = threadIdx.x;
    const int m0 = blockIdx.y * 128, n0 = blockIdx.x * 128;
    constexpr int NCH = K / 32;
    const int lane = tid & 31, wid = tid >> 5;
    const int g = lane >> 2, r = lane & 3;
    const int mw = (wid & 3) * 32, nw = (wid >> 2) * 64;

    // staging indices
    const int arow = tid >> 1, akh = (tid & 1) * 16;
    const int wn = tid & 127, wkh = (tid >> 7) * 16;
    const int wrow = n0 + wn;
    const float* wbase = (wrow < nsplit) ? (W0 + (size_t)wrow * K)
                                         : (W1 + (size_t)(wrow - nsplit) * K);

    float4 ra[4], rw[4];
    auto loadAB = [&](int ch) {
        const int kfA = ch * 32 + akh;
        #pragma unroll
        for (int q = 0; q < 4; ++q) {
            const int kk = kfA + q * 4;
            const float* ap;
            if (SPLITA) ap = (kk < 128) ? (A0 + (size_t)(m0 + arow) * 128 + kk)
                                        : (A1 + (size_t)(m0 + arow) * 128 + kk - 128);
            else        ap = A0 + (size_t)(m0 + arow) * K + kk;
            ra[q] = *(const float4*)ap;
        }
        const int kfW = ch * 32 + wkh;
        #pragma unroll
        for (int q = 0; q < 4; ++q)
            rw[q] = *(const float4*)(wbase + kfW + q * 4);
    };
    auto storeAB = [&](int buf) {
        uint32_t* Ab = Asm + buf * ASZ;
        uint32_t* Wb = Wsm + buf * WSZ;
        #pragma unroll
        for (int q = 0; q < 4; ++q) {
            uint4 t = make_uint4(tf32r(ra[q].x), tf32r(ra[q].y),
                                 tf32r(ra[q].z), tf32r(ra[q].w));
            *(uint4*)(Ab + arow * ASTR + akh + q * 4) = t;
        }
        #pragma unroll
        for (int q = 0; q < 4; ++q) {
            const int kb = wkh + q * 4;
            Wb[(kb + 0) * WSTR + wn] = tf32r(rw[q].x);
            Wb[(kb + 1) * WSTR + wn] = tf32r(rw[q].y);
            Wb[(kb + 2) * WSTR + wn] = tf32r(rw[q].z);
            Wb[(kb + 3) * WSTR + wn] = tf32r(rw[q].w);
        }
    };

    float acc[2][8][4];
    #pragma unroll
    for (int mt = 0; mt < 2; ++mt)
        #pragma unroll
        for (int nt = 0; nt < 8; ++nt)
            #pragma unroll
            for (int e = 0; e < 4; ++e) acc[mt][nt][e] = 0.f;

    loadAB(0);
    storeAB(0);
    __syncthreads();

    for (int ch = 0; ch < NCH; ++ch) {
        if (ch + 1 < NCH) loadAB(ch + 1);
        const uint32_t* Ab = Asm + (ch & 1) * ASZ;
        const uint32_t* Wb = Wsm + (ch & 1) * WSZ;
        #pragma unroll
        for (int ks = 0; ks < 4; ++ks) {
            const int kk = ks * 8;
            uint32_t af[2][4];
            #pragma unroll
            for (int mt = 0; mt < 2; ++mt) {
                const int rb = mw + mt * 16;
                af[mt][0] = Ab[(rb + g)     * ASTR + kk + r];
                af[mt][1] = Ab[(rb + g + 8) * ASTR + kk + r];
                af[mt][2] = Ab[(rb + g)     * ASTR + kk + r + 4];
                af[mt][3] = Ab[(rb + g + 8) * ASTR + kk + r + 4];
            }
            #pragma unroll
            for (int nt = 0; nt < 8; ++nt) {
                uint32_t bf[2];
                const int cb = nw + nt * 8 + g;
                bf[0] = Wb[(kk + r)     * WSTR + cb];
                bf[1] = Wb[(kk + r + 4) * WSTR + cb];
                mma8(acc[0][nt], af[0], bf);
                mma8(acc[1][nt], af[1], bf);
            }
        }
        if (ch + 1 < NCH) {
            __syncthreads();
            storeAB((ch + 1) & 1);
            __syncthreads();
        }
    }

    #pragma unroll
    for (int mt = 0; mt < 2; ++mt) {
        #pragma unroll
        for (int nt = 0; nt < 8; ++nt) {
            const int col = n0 + nw + nt * 8 + 2 * r;
            float b0 = 0.f, b1 = 0.f;
            if (bias) { b0 = bias[col]; b1 = bias[col + 1]; }
            float* c0 = C + (size_t)(m0 + mw + mt * 16 + g) * N + col;
            float* c1 = C + (size_t)(m0 + mw + mt * 16 + g + 8) * N + col;
            float2 v0 = make_float2(acc[mt][nt][0] + b0, acc[mt][nt][1] + b1);
            float2 v1 = make_float2(acc[mt][nt][2] + b0, acc[mt][nt][3] + b1);
            *(float2*)c0 = v0;
            *(float2*)c1 = v1;
        }
    }
}

// ================= E1: dual LayerNorm epilogue of G1 =================
__global__ __launch_bounds__(256)
void k_ln1(const float* __restrict__ pa_b, const float* __restrict__ pa_g,
           const float* __restrict__ pa_be,
           const float* __restrict__ pc_b, const float* __restrict__ pc_g,
           const float* __restrict__ pc_be)
{
    const int row  = blockIdx.x * 8 + (threadIdx.x >> 5);
    const int lane = threadIdx.x & 31;
    const float4* y4 = (const float4*)(g_y1 + (size_t)row * 384);

    float4 va = y4[lane];
    float4 b  = ((const float4*)pa_b)[lane];
    va.x += b.x; va.y += b.y; va.z += b.z; va.w += b.w;
    float m = wsum(va.x + va.y + va.z + va.w) * (1.f / 128.f);
    va.x -= m; va.y -= m; va.z -= m; va.w -= m;
    float inv = rsqrtf(wsum(va.x*va.x + va.y*va.y + va.z*va.z + va.w*va.w) * (1.f / 128.f) + EPSV);
    float4 g  = ((const float4*)pa_g)[lane];
    float4 be = ((const float4*)pa_be)[lane];
    float4 o;
    o.x = va.x * inv * g.x + be.x; o.y = va.y * inv * g.y + be.y;
    o.z = va.z * inv * g.z + be.z; o.w = va.w * inv * g.w + be.w;
    *(float4*)(g_xat + (size_t)row * 128 + lane * 4) = o;

    float4 c0 = y4[32 + lane], c1 = y4[64 + lane];
    float4 b0 = ((const float4*)pc_b)[lane], b1 = ((const float4*)pc_b)[32 + lane];
    c0.x += b0.x; c0.y += b0.y; c0.z += b0.z; c0.w += b0.w;
    c1.x += b1.x; c1.y += b1.y; c1.z += b1.z; c1.w += b1.w;
    m = wsum(c0.x + c0.y + c0.z + c0.w + c1.x + c1.y + c1.z + c1.w) * (1.f / 256.f);
    c0.x -= m; c0.y -= m; c0.z -= m; c0.w -= m;
    c1.x -= m; c1.y -= m; c1.z -= m; c1.w -= m;
    inv = rsqrtf(wsum(c0.x*c0.x + c0.y*c0.y + c0.z*c0.z + c0.w*c0.w +
                      c1.x*c1.x + c1.y*c1.y + c1.z*c1.z + c1.w*c1.w) * (1.f / 256.f) + EPSV);
    float4 g0 = ((const float4*)pc_g)[lane],  g1 = ((const float4*)pc_g)[32 + lane];
    float4 e0 = ((const float4*)pc_be)[lane], e1 = ((const float4*)pc_be)[32 + lane];
    float4 o0, o1;
    o0.x = c0.x * inv * g0.x + e0.x; o0.y = c0.y * inv * g0.y + e0.y;
    o0.z = c0.z * inv * g0.z + e0.z; o0.w = c0.w * inv * g0.w + e0.w;
    o1.x = c1.x * inv * g1.x + e1.x; o1.y = c1.y * inv * g1.y + e1.y;
    o1.z = c1.z * inv * g1.z + e1.z; o1.w = c1.w * inv * g1.w + e1.w;
    *(float4*)(g_xc + (size_t)row * 256 + lane * 4)       = o0;
    *(float4*)(g_xc + (size_t)row * 256 + 128 + lane * 4) = o1;
}

// ================= D: depthwise 3x3 + BN + GELU (window-major) ===========
__global__ __launch_bounds__(256)
void k_dw(const float* __restrict__ dw_w, const float* __restrict__ dw_b,
          const float* __restrict__ bn_g, const float* __restrict__ bn_b,
          const float* __restrict__ bn_m, const float* __restrict__ bn_v)
{
    extern __shared__ float sm[];   // 81 pixels x 256 ch
    const int bw = blockIdx.x, tid = threadIdx.x;
    const int b = bw >> 6, wi = bw & 63, wr = wi >> 3, wc = wi & 7;

    for (int i = tid; i < 81 * 64; i += 256) {
        int pix = i >> 6, c4 = i & 63;
        int gy = wr * 7 + pix / 9 - 1, gx = wc * 7 + pix % 9 - 1;
        float4 v = make_float4(0.f, 0.f, 0.f, 0.f);
        if ((unsigned)gy < 56u && (unsigned)gx < 56u) {
            int wn = b * 64 + (gy / 7) * 8 + gx / 7;
            int tk = (gy % 7) * 7 + gx % 7;
            v = *(const float4*)(g_xc + ((size_t)wn * 49 + tk) * 256 + c4 * 4);
        }
        *(float4*)(sm + pix * 256 + c4 * 4) = v;
    }
    __syncthreads();

    const int c = tid;
    float w[9];
    #pragma unroll
    for (int j = 0; j < 9; ++j) w[j] = dw_w[c * 9 + j];
    const float sc = bn_g[c] * rsqrtf(bn_v[c] + EPSV);
    const float sh = bn_b[c] - bn_m[c] * sc;
    const float db = dw_b[c];
    float* outp = g_d + (size_t)bw * 49 * 256;

    #pragma unroll 7
    for (int p = 0; p < 49; ++p) {
        int oy = p / 7, ox = p % 7;
        float acc = db;
        #pragma unroll
        for (int dy = 0; dy < 3; ++dy)
            #pragma unroll
            for (int dx = 0; dx < 3; ++dx)
                acc += w[dy * 3 + dx] * sm[((oy + dy) * 9 + ox + dx) * 256 + c];
        float v = acc * sc + sh;
        outp[p * 256 + c] = 0.5f * v * (1.0f + erff(v * 0.70710678118654752f));
    }
}

// ================= A: windowed MHSA + LN =================
__global__ __launch_bounds__(256)
void k_attn(const float* __restrict__ rpb,
            const float* __restrict__ an_g, const float* __restrict__ an_be)
{
    extern __shared__ float sm[];
    float* kvs  = sm;                 // 49*256 (k | v)
    float* ss   = sm + 49 * 256;      // 8*32*53 scores
    float* rpbs = ss + 8 * 32 * 53;   // 1352
    const int bw = blockIdx.x, tid = threadIdx.x;
    const int h = tid >> 5, lane = tid & 31;
    const float* qkvw = g_qkv + (size_t)bw * 49 * 384;

    for (int i = tid; i < 49 * 64; i += 256) {
        int r = i >> 6, cc = i & 63;
        *(float4*)(kvs + r * 256 + cc * 4) = *(const float4*)(qkvw + r * 384 + 128 + cc * 4);
    }
    for (int i = tid; i < 1352; i += 256) rpbs[i] = rpb[i];
    __syncthreads();

    float o[2][16];
    #pragma unroll
    for (int pass = 0; pass < 2; ++pass) {
        const int n = pass * 32 + lane;
        if (n < 49) {
            float q[16];
            const float4* qp = (const float4*)(qkvw + n * 384 + h * 16);
            *(float4*)&q[0]  = qp[0]; *(float4*)&q[4]  = qp[1];
            *(float4*)&q[8]  = qp[2]; *(float4*)&q[12] = qp[3];
            const int yn = n / 7, xn = n % 7;
            float* sr = ss + (h * 32 + lane) * 53;
            float mx = -1e30f;
            #pragma unroll 7
            for (int m2 = 0; m2 < 49; ++m2) {
                const float* kr = kvs + m2 * 256 + h * 16;
                float s = 0.f;
                #pragma unroll
                for (int d = 0; d < 16; ++d) s += q[d] * kr[d];
                int dy = yn - m2 / 7 + 6, dx = xn - m2 % 7 + 6;
                s = s * 0.25f + rpbs[(dy * 13 + dx) * NH + h];
                sr[m2] = s; mx = fmaxf(mx, s);
            }
            float sum = 0.f;
            #pragma unroll 7
            for (int m2 = 0; m2 < 49; ++m2) {
                float e = __expf(sr[m2] - mx);
                sr[m2] = e; sum += e;
            }
            const float inv = 1.f / sum;
            float* op = o[pass];
            #pragma unroll
            for (int d = 0; d < 16; ++d) op[d] = 0.f;
            #pragma unroll 7
            for (int m2 = 0; m2 < 49; ++m2) {
                float p = sr[m2];
                const float* vr = kvs + m2 * 256 + 128 + h * 16;
                #pragma unroll
                for (int d = 0; d < 16; ++d) op[d] += p * vr[d];
            }
            #pragma unroll
            for (int d = 0; d < 16; ++d) op[d] *= inv;
        }
    }
    __syncthreads();
    float* xo = kvs;
    #pragma unroll
    for (int pass = 0; pass < 2; ++pass) {
        const int n = pass * 32 + lane;
        if (n < 49) {
            #pragma unroll
            for (int d = 0; d < 16; ++d) xo[n * 128 + h * 16 + d] = o[pass][d];
        }
    }
    __syncthreads();

    for (int r = h; r < 49; r += 8) {
        float4 v = *(float4*)(xo + r * 128 + lane * 4);
        float m = wsum(v.x + v.y + v.z + v.w) * (1.f / 128.f);
        v.x -= m; v.y -= m; v.z -= m; v.w -= m;
        float inv = rsqrtf(wsum(v.x*v.x + v.y*v.y + v.z*v.z + v.w*v.w) * (1.f / 128.f) + EPSV);
        float4 g  = ((const float4*)an_g)[lane];
        float4 be = ((const float4*)an_be)[lane];
        float4 out;
        out.x = v.x * inv * g.x + be.x; out.y = v.y * inv * g.y + be.y;
        out.z = v.z * inv * g.z + be.z; out.w = v.w * inv * g.w + be.w;
        *(float4*)(g_xat2 + ((size_t)bw * 49 + r) * 128 + lane * 4) = out;
    }
}

// ================= host launch =================
extern "C" void kernel_launch(void* const* d_in, const int* in_sizes, int n_in,
                              void* d_out, int out_size)
{
    const float* x     = (const float*)d_in[0];
    const float* rpb   = (const float*)d_in[1];
    const float* pa_w  = (const float*)d_in[2];
    const float* pa_b  = (const float*)d_in[3];
    const float* pa_g  = (const float*)d_in[4];
    const float* pa_be = (const float*)d_in[5];
    const float* pc_w  = (const float*)d_in[6];
    const float* pc_b  = (const float*)d_in[7];
    const float* pc_g  = (const float*)d_in[8];
    const float* pc_be = (const float*)d_in[9];
    const float* dw_w  = (const float*)d_in[10];
    const float* dw_b  = (const float*)d_in[11];
    const float* bn_g  = (const float*)d_in[12];
    const float* bn_b  = (const float*)d_in[13];
    const float* bn_m  = (const float*)d_in[14];
    const float* bn_v  = (const float*)d_in[15];
    const float* pr_w  = (const float*)d_in[16];
    const float* pr_b  = (const float*)d_in[17];
    const float* qkv_w = (const float*)d_in[18];
    const float* qkv_b = (const float*)d_in[19];
    const float* an_g  = (const float*)d_in[20];
    const float* an_be = (const float*)d_in[21];
    const float* po_w  = (const float*)d_in[22];
    const float* po_b  = (const float*)d_in[23];

    float *py1, *pxat, *pxc, *pd, *pqkv, *pxcw, *pxat2;
    cudaGetSymbolAddress((void**)&py1,   g_y1);
    cudaGetSymbolAddress((void**)&pxat,  g_xat);
    cudaGetSymbolAddress((void**)&pxc,   g_xc);
    cudaGetSymbolAddress((void**)&pd,    g_d);
    cudaGetSymbolAddress((void**)&pqkv,  g_qkv);
    cudaGetSymbolAddress((void**)&pxcw,  g_xcw);
    cudaGetSymbolAddress((void**)&pxat2, g_xat2);

    const int smG = (2 * ASZ + 2 * WSZ) * 4;      // 71,680
    const int smD = 81 * 256 * 4;                 // 82,944
    const int smA = (49*256 + 8*32*53 + 1352) * 4;// 109,856

    cudaFuncSetAttribute(k_gemm<256,false>, cudaFuncAttributeMaxDynamicSharedMemorySize, smG);
    cudaFuncSetAttribute(k_gemm<128,false>, cudaFuncAttributeMaxDynamicSharedMemorySize, smG);
    cudaFuncSetAttribute(k_gemm<256,true>,  cudaFuncAttributeMaxDynamicSharedMemorySize, smG);
    cudaFuncSetAttribute(k_dw,   cudaFuncAttributeMaxDynamicSharedMemorySize, smD);
    cudaFuncSetAttribute(k_attn, cudaFuncAttributeMaxDynamicSharedMemorySize, smA);

    const int MT = M_TOT / 128;   // 784

    // G1: x @ [pa_w; pc_w]^T -> g_y1 (bias deferred to LN)
    k_gemm<256,false><<<dim3(3, MT), 256, smG>>>(x, nullptr, pa_w, pc_w, 128,
                                                 nullptr, py1, 384);
    // E1: dual LN -> g_xat, g_xc
    k_ln1<<<M_TOT/8, 256>>>(pa_b, pa_g, pa_be, pc_b, pc_g, pc_be);
    // G3: qkv = g_xat @ qkv_w^T + qkv_b
    k_gemm<128,false><<<dim3(3, MT), 256, smG>>>(pxat, nullptr, qkv_w, qkv_w, 1<<30,
                                                 qkv_b, pqkv, 384);
    // D: dwconv + BN + GELU -> g_d
    k_dw<<<BW_, 256, smD>>>(dw_w, dw_b, bn_g, bn_b, bn_m, bn_v);
    // G2: 1x1 conv: g_d @ pr_w^T + pr_b -> g_xcw
    k_gemm<256,false><<<dim3(1, MT), 256, smG>>>(pd, nullptr, pr_w, pr_w, 1<<30,
                                                 pr_b, pxcw, 128);
    // A: attention + LN -> g_xat2
    k_attn<<<BW_, 256, smA>>>(rpb, an_g, an_be);
    // G4: concat(g_xat2, g_xcw) @ po_w^T + po_b -> out
    k_gemm<256,true><<<dim3(2, MT), 256, smG>>>(pxat2, pxcw, po_w, po_w, 1<<30,
                                                po_b, (float*)d_out, 256);
}